// round 14
// baseline (speedup 1.0000x reference)
#include <cuda_runtime.h>
#include <math.h>
#include <stdint.h>

#define D_MODEL 1024
#define N_HEADS 16
#define K_WIN   8
#define BATCH   2
#define SEQ     2048
#define M_TOTAL (BATCH * SEQ)          // 4096 tokens
#define QKV_COLS (3 * D_MODEL)         // 3072
#define K2      (2 * D_MODEL)          // 2048 tf32 cols (hi/lo interleaved)

// ---------------------------------------------------------------------------
// Scratch (__device__ globals, uint4-backed for 16B alignment).
// g_as (attention split output) aliases g_xs: x-split is dead after GEMM1.
// ---------------------------------------------------------------------------
__device__ uint4 g_qkv4[((size_t)M_TOTAL * QKV_COLS * 4) / 16];   // fp32 qkv (50 MB)
__device__ uint4 g_xs4 [((size_t)M_TOTAL * K2 * 4) / 16];         // tf32 split x / attn (33 MB)
__device__ uint4 g_wq4 [((size_t)QKV_COLS * K2 * 4) / 16];        // tf32 split qkv_w (25 MB)
__device__ uint4 g_wo4 [((size_t)D_MODEL * K2 * 4) / 16];         // tf32 split out_w (8 MB)

#define G_QKV ((float*)g_qkv4)
#define G_XS  ((uint32_t*)g_xs4)
#define G_WQ  ((uint32_t*)g_wq4)
#define G_WO  ((uint32_t*)g_wo4)
#define G_AS  ((uint32_t*)g_xs4)

// ---------------------------------------------------------------------------
// tf32 split: x = hi + lo (both tf32-representable), stored interleaved.
// ---------------------------------------------------------------------------
__device__ __forceinline__ uint32_t f2tf(float x) {
    uint32_t r;
    asm("cvt.rna.tf32.f32 %0, %1;" : "=r"(r) : "f"(x));
    return r;
}
__device__ __forceinline__ void tfpair(float x, uint32_t& hi, uint32_t& lo) {
    hi = f2tf(x);
    lo = f2tf(x - __uint_as_float(hi));
}

// mode: 0 -> G_XS, 1 -> G_WQ, 2 -> G_WO
__global__ __launch_bounds__(256)
void split_kernel(const float* __restrict__ src, int mode, int n4)
{
    int i = blockIdx.x * blockDim.x + threadIdx.x;
    if (i >= n4) return;
    uint32_t* dst = (mode == 0) ? G_XS : (mode == 1) ? G_WQ : G_WO;
    float4 v = __ldg((const float4*)src + i);
    uint4 h0, h1;
    tfpair(v.x, h0.x, h0.y);
    tfpair(v.y, h0.z, h0.w);
    tfpair(v.z, h1.x, h1.y);
    tfpair(v.w, h1.z, h1.w);
    *((uint4*)dst + 2 * i)     = h0;
    *((uint4*)dst + 2 * i + 1) = h1;
}

// ---------------------------------------------------------------------------
// tf32 mma.sync GEMM on pre-split operands:
// C[M,N] = A[M,K2]tf32 @ B[N,K2]tf32^T + bias (fp32 out)
// CTA tile 128x128, K-chunk 32 tf32 cols, 256 threads / 8 warps (64x32 warp
// tile, 64 fp32 accs). Loader: 1024 uint4 chunks PER OPERAND, 4 per thread
// per operand (full row coverage — R13's bug was 2/operand, half-filled).
// ---------------------------------------------------------------------------
#define BM   128
#define BN   128
#define BKT  32
#define PADT 36              // smem row: 32 u32 + 4 pad words

__device__ __forceinline__
void tf32_gemm_body(const uint32_t* __restrict__ A,
                    const uint32_t* __restrict__ B,
                    const float* __restrict__ bias,
                    float* __restrict__ C,
                    int N)
{
    __shared__ uint32_t As[BM][PADT];
    __shared__ uint32_t Bs[BN][PADT];

    const int tid    = threadIdx.x;
    const int wid    = tid >> 5;
    const int lane   = tid & 31;
    const int g      = lane >> 2;      // group 0..7
    const int t      = lane & 3;       // thread-in-group
    const int warp_m = wid & 1;        // 0..1 (64-row slabs)
    const int warp_n = wid >> 1;       // 0..3 (32-col slabs)

    const int bm = blockIdx.y * BM;
    const int bn = blockIdx.x * BN;
    const uint32_t* Arow = A + (size_t)bm * K2;
    const uint32_t* Brow = B + (size_t)bn * K2;

    // Loader: chunk u -> row = u>>3 (0..127), col4 = (u&7)*4 (0..28).
    // Each thread covers chunks tid, tid+256, tid+512, tid+768 for BOTH operands.
    const int r0 = tid >> 3,         c40 = (tid & 7) * 4;
    const int r1 = (tid + 256) >> 3, c41 = ((tid + 256) & 7) * 4;
    const int r2 = (tid + 512) >> 3, c42 = ((tid + 512) & 7) * 4;
    const int r3 = (tid + 768) >> 3, c43 = ((tid + 768) & 7) * 4;

    float acc[4][4][4];
#pragma unroll
    for (int i = 0; i < 4; i++)
#pragma unroll
        for (int j = 0; j < 4; j++)
#pragma unroll
            for (int e = 0; e < 4; e++) acc[i][j][e] = 0.f;

    const int NITER = K2 / BKT;     // 64

    for (int c = 0; c < NITER; c++) {
        const int k0 = c * BKT;
        {
            const uint4 a0v = *(const uint4*)(Arow + (size_t)r0 * K2 + k0 + c40);
            const uint4 a1v = *(const uint4*)(Arow + (size_t)r1 * K2 + k0 + c41);
            const uint4 a2v = *(const uint4*)(Arow + (size_t)r2 * K2 + k0 + c42);
            const uint4 a3v = *(const uint4*)(Arow + (size_t)r3 * K2 + k0 + c43);
            const uint4 b0v = *(const uint4*)(Brow + (size_t)r0 * K2 + k0 + c40);
            const uint4 b1v = *(const uint4*)(Brow + (size_t)r1 * K2 + k0 + c41);
            const uint4 b2v = *(const uint4*)(Brow + (size_t)r2 * K2 + k0 + c42);
            const uint4 b3v = *(const uint4*)(Brow + (size_t)r3 * K2 + k0 + c43);
            *(uint4*)&As[r0][c40] = a0v;
            *(uint4*)&As[r1][c41] = a1v;
            *(uint4*)&As[r2][c42] = a2v;
            *(uint4*)&As[r3][c43] = a3v;
            *(uint4*)&Bs[r0][c40] = b0v;
            *(uint4*)&Bs[r1][c41] = b1v;
            *(uint4*)&Bs[r2][c42] = b2v;
            *(uint4*)&Bs[r3][c43] = b3v;
        }
        __syncthreads();

#pragma unroll
        for (int s = 0; s < 4; s++) {
            const int kb = s * 8;
            const uint32_t b00 = Bs[warp_n * 32 + 0 * 8 + g][kb + t];
            const uint32_t b01 = Bs[warp_n * 32 + 0 * 8 + g][kb + t + 4];
            const uint32_t b10 = Bs[warp_n * 32 + 1 * 8 + g][kb + t];
            const uint32_t b11 = Bs[warp_n * 32 + 1 * 8 + g][kb + t + 4];
            const uint32_t b20 = Bs[warp_n * 32 + 2 * 8 + g][kb + t];
            const uint32_t b21 = Bs[warp_n * 32 + 2 * 8 + g][kb + t + 4];
            const uint32_t b30 = Bs[warp_n * 32 + 3 * 8 + g][kb + t];
            const uint32_t b31 = Bs[warp_n * 32 + 3 * 8 + g][kb + t + 4];
#pragma unroll
            for (int mf = 0; mf < 4; mf++) {
                const int mr = warp_m * 64 + mf * 16;
                const uint32_t a0 = As[mr + g    ][kb + t];
                const uint32_t a1 = As[mr + g + 8][kb + t];
                const uint32_t a2 = As[mr + g    ][kb + t + 4];
                const uint32_t a3 = As[mr + g + 8][kb + t + 4];
#define TF32_MMA(nf, bb0, bb1)                                          \
                asm volatile(                                           \
                    "mma.sync.aligned.m16n8k8.row.col.f32.tf32.tf32.f32 " \
                    "{%0,%1,%2,%3}, {%4,%5,%6,%7}, {%8,%9}, {%0,%1,%2,%3};" \
                    : "+f"(acc[mf][nf][0]), "+f"(acc[mf][nf][1]),       \
                      "+f"(acc[mf][nf][2]), "+f"(acc[mf][nf][3])        \
                    : "r"(a0), "r"(a1), "r"(a2), "r"(a3), "r"(bb0), "r"(bb1))
                TF32_MMA(0, b00, b01);
                TF32_MMA(1, b10, b11);
                TF32_MMA(2, b20, b21);
                TF32_MMA(3, b30, b31);
#undef TF32_MMA
            }
        }
        __syncthreads();
    }

    // Epilogue: acc e0,e1 -> (row g, cols 2t,2t+1); e2,e3 -> (row g+8).
#pragma unroll
    for (int mf = 0; mf < 4; mf++) {
        const int gr = bm + warp_m * 64 + mf * 16 + g;
#pragma unroll
        for (int nf = 0; nf < 4; nf++) {
            const int gc = bn + warp_n * 32 + nf * 8 + t * 2;
            const float b0 = __ldg(bias + gc);
            const float b1 = __ldg(bias + gc + 1);
            float2 v0 = make_float2(acc[mf][nf][0] + b0, acc[mf][nf][1] + b1);
            float2 v1 = make_float2(acc[mf][nf][2] + b0, acc[mf][nf][3] + b1);
            *(float2*)(C + (size_t)gr * N + gc)       = v0;
            *(float2*)(C + (size_t)(gr + 8) * N + gc) = v1;
        }
    }
}

__global__ __launch_bounds__(256)
void tf32_x_to_qkv(const float* __restrict__ qkv_b)
{
    tf32_gemm_body(G_XS, G_WQ, qkv_b, G_QKV, QKV_COLS);
}

__global__ __launch_bounds__(256)
void tf32_att_to_out(const float* __restrict__ out_b, float* __restrict__ out)
{
    tf32_gemm_body(G_AS, G_WO, out_b, out, D_MODEL);
}

// ---------------------------------------------------------------------------
// QK-norm: L2-normalize each 64-element head vector of q and k (in place).
// (R11-proven)
// ---------------------------------------------------------------------------
__global__ __launch_bounds__(256)
void qknorm_kernel()
{
    int gw   = (blockIdx.x * blockDim.x + threadIdx.x) >> 5;
    int lane = threadIdx.x & 31;
    if (gw >= M_TOTAL * 32) return;
    int row = gw >> 5;
    int seg = gw & 31;
    size_t off = (size_t)row * QKV_COLS +
                 (seg < 16 ? seg * 64 : D_MODEL + (seg - 16) * 64);
    float* p = G_QKV + off;
    float2 v = *(float2*)(p + lane * 2);
    float ss = v.x * v.x + v.y * v.y;
#pragma unroll
    for (int o = 16; o; o >>= 1) ss += __shfl_xor_sync(0xFFFFFFFFu, ss, o);
    float inv = 1.0f / (sqrtf(ss) + 1e-6f);
    v.x *= inv; v.y *= inv;
    *(float2*)(p + lane * 2) = v;
}

// ---------------------------------------------------------------------------
// Dilated attention: one warp per (token, head). Output written pre-split
// (tf32 hi/lo interleaved) into G_AS for the second GEMM.
// ---------------------------------------------------------------------------
__global__ __launch_bounds__(256)
void attend_kernel()
{
    int gw   = (blockIdx.x * blockDim.x + threadIdx.x) >> 5;
    int lane = threadIdx.x & 31;
    if (gw >= M_TOTAL * N_HEADS) return;
    int r = gw >> 4;
    int h = gw & 15;
    int b = r / SEQ;
    int i = r % SEQ;

    const float* qp = G_QKV + (size_t)r * QKV_COLS + h * 64;
    const float* kb = G_QKV + (size_t)(b * SEQ) * QKV_COLS + D_MODEL + h * 64;
    const float* vb = G_QKV + (size_t)(b * SEQ) * QKV_COLS + 2 * D_MODEL + h * 64;

    float2 q = *(const float2*)(qp + lane * 2);

    float sc[17];
#pragma unroll
    for (int t = 0; t < 17; t++) {
        int j = i + 2 * (t - K_WIN);
        float s = -INFINITY;
        if (j >= 0 && j < SEQ) {
            float2 k = *(const float2*)(kb + (size_t)j * QKV_COLS + lane * 2);
            float d = q.x * k.x + q.y * k.y;
#pragma unroll
            for (int o = 16; o; o >>= 1) d += __shfl_xor_sync(0xFFFFFFFFu, d, o);
            s = d;
        }
        sc[t] = s;
    }

    float mx = -INFINITY;
#pragma unroll
    for (int t = 0; t < 17; t++) mx = fmaxf(mx, sc[t]);
    float den = 0.f;
#pragma unroll
    for (int t = 0; t < 17; t++) {
        float e = (sc[t] == -INFINITY) ? 0.f : __expf(sc[t] - mx);
        sc[t] = e;
        den += e;
    }
    float inv = 1.0f / den;   // den >= 1: diagonal always in window

    float2 acc = make_float2(0.f, 0.f);
#pragma unroll
    for (int t = 0; t < 17; t++) {
        int j = i + 2 * (t - K_WIN);
        if (j >= 0 && j < SEQ) {
            float2 v = *(const float2*)(vb + (size_t)j * QKV_COLS + lane * 2);
            float p = sc[t] * inv;
            acc.x = fmaf(p, v.x, acc.x);
            acc.y = fmaf(p, v.y, acc.y);
        }
    }

    // tf32 hi/lo split, interleaved: elem col e -> split cols 2e, 2e+1.
    // e = h*64 + lane*2 (even) -> 2e is a multiple of 4: uint4-aligned.
    uint4 w;
    tfpair(acc.x, w.x, w.y);
    tfpair(acc.y, w.z, w.w);
    *(uint4*)(G_AS + (size_t)r * K2 + 2 * (h * 64 + lane * 2)) = w;
}

// ---------------------------------------------------------------------------
// Launch (pure kernel launches; graph-capture safe)
// ---------------------------------------------------------------------------
extern "C" void kernel_launch(void* const* d_in, const int* in_sizes, int n_in,
                              void* d_out, int out_size)
{
    const float* x     = (const float*)d_in[0];
    const float* qkv_w = (const float*)d_in[1];
    const float* qkv_b = (const float*)d_in[2];
    const float* out_w = (const float*)d_in[3];
    const float* out_b = (const float*)d_in[4];
    float* out = (float*)d_out;

    // 0) Split prepasses (fp32 -> interleaved tf32 hi/lo)
    {
        int n4 = (M_TOTAL * D_MODEL) / 4;
        split_kernel<<<n4 / 256, 256>>>(x, 0, n4);
    }
    {
        int n4 = (QKV_COLS * D_MODEL) / 4;
        split_kernel<<<n4 / 256, 256>>>(qkv_w, 1, n4);
    }
    {
        int n4 = (D_MODEL * D_MODEL) / 4;
        split_kernel<<<n4 / 256, 256>>>(out_w, 2, n4);
    }

    // 1) QKV projection: G_XS @ G_WQ^T + qkv_b -> G_QKV fp32 (4096x3072)
    {
        dim3 grid(QKV_COLS / BN, M_TOTAL / BM);
        tf32_x_to_qkv<<<grid, 256>>>(qkv_b);
    }

    // 2) QK L2-normalization (in place on G_QKV)
    qknorm_kernel<<<(M_TOTAL * 32) / 8, 256>>>();

    // 3) Dilated windowed attention -> G_AS (tf32 hi/lo; aliases G_XS)
    attend_kernel<<<(M_TOTAL * N_HEADS) / 8, 256>>>();

    // 4) Output projection: G_AS @ G_WO^T + out_b -> out fp32 (4096x1024)
    {
        dim3 grid(D_MODEL / BN, M_TOTAL / BM);
        tf32_att_to_out<<<grid, 256>>>(out_b, out);
    }
}